// round 3
// baseline (speedup 1.0000x reference)
#include <cuda_runtime.h>
#include <cuda_bf16.h>
#include <mma.h>
#include <math.h>

using namespace nvcuda;

// Problem constants
#define C_DIM   256
#define M_CLS   256
#define HW      16384
#define N_PIX   262144
#define TILE_P  128
#define KB      32
#define NBLOCKS (N_PIX / TILE_P)      // 2048
#define NTHREADS 512
#define INV_T   14.2857142857142857f  // 1/0.07

// smem layout (bytes)
#define LDA 136    // A: [KB][TILE_P+8] bf16, col-major A (pixel contiguous)
#define LDB 40     // B: [M_CLS][KB+8] bf16, col-major B (channel contiguous)
#define LDL 264    // logits: [TILE_P][M_CLS+8] f32
#define A_BUF_BYTES (KB * LDA * 2)        // 8704
#define B_BUF_BYTES (M_CLS * LDB * 2)     // 20480
#define A0_OFF 0
#define A1_OFF (A_BUF_BYTES)              // 8704
#define B0_OFF (2 * A_BUF_BYTES)          // 17408
#define B1_OFF (B0_OFF + B_BUF_BYTES)     // 37888
#define LOGITS_BYTES (TILE_P * LDL * 4)   // 135168
#define RED_OFF LOGITS_BYTES
#define SMEM_BYTES (LOGITS_BYTES + 128)   // 135296

__device__ float2 g_partials[NBLOCKS];
__device__ __nv_bfloat16 g_queue_bf[M_CLS * C_DIM];
__device__ unsigned int g_done;   // zero-initialized; reset to 0 by last block each launch

// ---- tiny pre-pass: queue f32 -> bf16 (runs once per launch, ~2us) ----
__global__ void queue_to_bf16_kernel(const float* __restrict__ queue)
{
    int i = (blockIdx.x * blockDim.x + threadIdx.x) * 2;
    float2 v = *(const float2*)(queue + i);
    __nv_bfloat162 b;
    b.x = __float2bfloat16(v.x);
    b.y = __float2bfloat16(v.y);
    *(__nv_bfloat162*)(g_queue_bf + i) = b;
}

__global__ __launch_bounds__(NTHREADS, 1)
void pcl_fused_kernel(const float* __restrict__ feats,
                      const int*   __restrict__ labels,
                      float*       __restrict__ out)
{
    extern __shared__ char smem_raw[];
    __nv_bfloat16* Abuf[2] = { (__nv_bfloat16*)(smem_raw + A0_OFF),
                               (__nv_bfloat16*)(smem_raw + A1_OFF) };
    __nv_bfloat16* Bbuf[2] = { (__nv_bfloat16*)(smem_raw + B0_OFF),
                               (__nv_bfloat16*)(smem_raw + B1_OFF) };
    float* Ls  = (float*)smem_raw;                 // union with stage bufs (used after loop)
    float* red = (float*)(smem_raw + RED_OFF);     // [32]

    const int tid  = threadIdx.x;
    const int warp = tid >> 5;
    const int lane = tid & 31;
    const int pix0 = blockIdx.x * TILE_P;

    // feats [b,c,h,w]; TILE_P divides HW so a CTA never crosses an image.
    const float* fbase = feats + (size_t)(pix0 / HW) * C_DIM * HW + (pix0 % HW);

    const int wm = warp & 3;    // pixel warp coord (0..3) -> offset wm*32
    const int wn = warp >> 2;   // class warp coord (0..3) -> offset wn*64

    const int pixl = tid & 127;   // A staging: pixel lane
    const int chb  = tid >> 7;    // A staging: channel group (0..3)
    const int bcls = tid >> 2;    // B staging: class (0..127 for first half)
    const int bkg  = tid & 3;     // B staging: 8-channel group within chunk

    wmma::fragment<wmma::accumulator, 16, 16, 16, float> acc[2][4];
    #pragma unroll
    for (int i = 0; i < 2; i++)
        #pragma unroll
        for (int j = 0; j < 4; j++)
            wmma::fill_fragment(acc[i][j], 0.0f);

    // register-staged prefetch
    float areg[8];
    uint4 breg[2];

    auto load_chunk = [&](int ks) {
        #pragma unroll
        for (int it = 0; it < 8; it++) {
            int ch = chb + it * 4;
            areg[it] = __ldg(fbase + (size_t)(ks * KB + ch) * HW + pixl);
        }
        #pragma unroll
        for (int it = 0; it < 2; it++) {
            int cls = bcls + it * 128;
            breg[it] = *(const uint4*)(g_queue_bf + cls * C_DIM + ks * KB + bkg * 8);
        }
    };
    auto store_chunk = [&](int buf) {
        #pragma unroll
        for (int it = 0; it < 8; it++) {
            int ch = chb + it * 4;
            Abuf[buf][ch * LDA + pixl] = __float2bfloat16(areg[it]);
        }
        #pragma unroll
        for (int it = 0; it < 2; it++) {
            int cls = bcls + it * 128;
            *(uint4*)(Bbuf[buf] + cls * LDB + bkg * 8) = breg[it];
        }
    };

    load_chunk(0);
    store_chunk(0);
    __syncthreads();

    #pragma unroll 1
    for (int ks = 0; ks < C_DIM / KB; ks++) {
        if (ks < C_DIM / KB - 1) load_chunk(ks + 1);   // LDG latency hides under MMA

        const __nv_bfloat16* As = Abuf[ks & 1];
        const __nv_bfloat16* Bs = Bbuf[ks & 1];
        #pragma unroll
        for (int kf = 0; kf < KB / 16; kf++) {
            wmma::fragment<wmma::matrix_a, 16, 16, 16, __nv_bfloat16, wmma::col_major> af[2];
            wmma::fragment<wmma::matrix_b, 16, 16, 16, __nv_bfloat16, wmma::col_major> bf[4];
            #pragma unroll
            for (int i = 0; i < 2; i++)
                wmma::load_matrix_sync(af[i], As + kf * 16 * LDA + wm * 32 + i * 16, LDA);
            #pragma unroll
            for (int j = 0; j < 4; j++)
                wmma::load_matrix_sync(bf[j], Bs + (wn * 64 + j * 16) * LDB + kf * 16, LDB);
            #pragma unroll
            for (int i = 0; i < 2; i++)
                #pragma unroll
                for (int j = 0; j < 4; j++)
                    wmma::mma_sync(acc[i][j], af[i], bf[j], acc[i][j]);
        }

        if (ks < C_DIM / KB - 1) {
            store_chunk((ks + 1) & 1);
            __syncthreads();
        }
    }

    __syncthreads();   // stage smem dead; reuse as logits tile
    #pragma unroll
    for (int i = 0; i < 2; i++)
        #pragma unroll
        for (int j = 0; j < 4; j++)
            wmma::store_matrix_sync(Ls + (wm * 32 + i * 16) * LDL + wn * 64 + j * 16,
                                    acc[i][j], LDL, wmma::mem_row_major);
    __syncthreads();

    // ---- fused epilogue: 4 threads (one quad) per pixel, 64 classes each ----
    const int pix = tid >> 2;
    const int qd  = tid & 3;
    const float* lrow = Ls + pix * LDL + qd * 64;
    const int4*  lab  = (const int4*)(labels + (size_t)(pix0 + pix) * M_CLS + qd * 64);

    float sn = 0.0f, sp = 0.0f;
    #pragma unroll
    for (int j = 0; j < 16; j++) {
        int4   l4 = lab[j];
        float4 d4 = ((const float4*)lrow)[j];
        { float s = d4.x * INV_T; float e = __expf(l4.x ? -s : s); if (l4.x) sp += e; else sn += e; }
        { float s = d4.y * INV_T; float e = __expf(l4.y ? -s : s); if (l4.y) sp += e; else sn += e; }
        { float s = d4.z * INV_T; float e = __expf(l4.z ? -s : s); if (l4.z) sp += e; else sn += e; }
        { float s = d4.w * INV_T; float e = __expf(l4.w ? -s : s); if (l4.w) sp += e; else sn += e; }
    }
    sn += __shfl_xor_sync(0xFFFFFFFFu, sn, 1);
    sn += __shfl_xor_sync(0xFFFFFFFFu, sn, 2);
    sp += __shfl_xor_sync(0xFFFFFFFFu, sp, 1);
    sp += __shfl_xor_sync(0xFFFFFFFFu, sp, 2);

    float th_loss = 0.0f, th_cnt = 0.0f;
    if (qd == 0) {
        float loss = logf(sn * sp + 1.0f);
        th_loss = loss;
        th_cnt  = (loss != 0.0f) ? 1.0f : 0.0f;
    }
    #pragma unroll
    for (int o = 16; o > 0; o >>= 1) {
        th_loss += __shfl_xor_sync(0xFFFFFFFFu, th_loss, o);
        th_cnt  += __shfl_xor_sync(0xFFFFFFFFu, th_cnt,  o);
    }
    if (lane == 0) { red[warp * 2] = th_loss; red[warp * 2 + 1] = th_cnt; }
    __syncthreads();

    __shared__ bool is_last;
    if (tid == 0) {
        float s = 0.0f, c = 0.0f;
        #pragma unroll
        for (int w = 0; w < 16; w++) { s += red[2 * w]; c += red[2 * w + 1]; }
        g_partials[blockIdx.x] = make_float2(s, c);
        __threadfence();
        unsigned old = atomicAdd(&g_done, 1u);
        is_last = (old == NBLOCKS - 1);
    }
    __syncthreads();

    // ---- last arriving block performs the deterministic final reduction ----
    if (is_last) {
        double s = 0.0;
        float  c = 0.0f;
        #pragma unroll
        for (int it = 0; it < NBLOCKS / NTHREADS; it++) {
            float2 p = g_partials[tid + it * NTHREADS];
            s += (double)p.x;
            c += p.y;
        }
        __shared__ double ssum[NTHREADS];
        __shared__ float  scnt[NTHREADS];
        ssum[tid] = s;
        scnt[tid] = c;
        __syncthreads();
        for (int o = NTHREADS / 2; o > 0; o >>= 1) {
            if (tid < o) { ssum[tid] += ssum[tid + o]; scnt[tid] += scnt[tid + o]; }
            __syncthreads();
        }
        if (tid == 0) {
            float cnt = scnt[0];
            out[0] = (cnt == 0.0f) ? 0.0f : (float)(ssum[0] / (double)fmaxf(cnt, 1.0f));
            __threadfence();
            g_done = 0;   // reset for next (graph-replayed) launch
        }
    }
}

extern "C" void kernel_launch(void* const* d_in, const int* in_sizes, int n_in,
                              void* d_out, int out_size)
{
    // metadata.txt order: feats (f32), queue (f32), labels (i32).
    // feats and labels have identical element counts — positional ID only.
    const float* feats  = (const float*)d_in[0];
    const float* queue  = (const float*)d_in[1];
    const int*   labels = (const int*)d_in[2];

    cudaFuncSetAttribute(pcl_fused_kernel,
                         cudaFuncAttributeMaxDynamicSharedMemorySize, SMEM_BYTES);

    queue_to_bf16_kernel<<<M_CLS * C_DIM / (2 * 256), 256>>>(queue);
    pcl_fused_kernel<<<NBLOCKS, NTHREADS, SMEM_BYTES>>>(feats, labels, (float*)d_out);
}

// round 5
// speedup vs baseline: 1.7060x; 1.7060x over previous
#include <cuda_runtime.h>
#include <cuda_bf16.h>
#include <cstdint>
#include <math.h>

// ---------------- problem constants ----------------
#define C_DIM   256
#define M_CLS   256
#define HW      16384
#define N_PIX   262144
#define TILE_P  128
#define KB      32                    // channels per A chunk
#define NKS     (C_DIM / KB)          // 8
#define NBLOCKS (N_PIX / TILE_P)      // 2048
#define NTHREADS 512
#define INV_T   14.2857142857142857f  // 1/0.07

// ---------------- smem layout (bytes) ----------------
// B: full queue tile, 256 cls x 256 ch bf16, row = 512B, XOR-swizzled
#define SM_B    0
#define B_BYTES (M_CLS * C_DIM * 2)        // 131072
// A: double-buffered chunk, 128 pix x 32 ch bf16, row = 64B, XOR-swizzled
#define SM_A0   (B_BYTES)                  // 131072
#define SM_A1   (SM_A0 + TILE_P * KB * 2)  // 139264
#define SM_RED  (SM_A1 + TILE_P * KB * 2)  // 147456: sn[4][128], sp[4][128], wpart[8]
#define SMEM_BYTES (SM_RED + 4096 + 64)    // 151616

__device__ float2 g_partials[NBLOCKS];
__device__ __align__(16) __nv_bfloat16 g_queue_bf[M_CLS * C_DIM];
__device__ unsigned int g_done;   // zero-init; reset by last block each launch

__device__ __forceinline__ uint32_t smem_u32(const void* p) {
    uint32_t a;
    asm("{ .reg .u64 t; cvta.to.shared.u64 t, %1; cvt.u32.u64 %0, t; }" : "=r"(a) : "l"(p));
    return a;
}
__device__ __forceinline__ uint32_t pkbf2(float x, float y) {
    __nv_bfloat162 h = __floats2bfloat162_rn(x, y);
    return *(uint32_t*)&h;
}
#define CP_ASYNC16(dst, src) \
    asm volatile("cp.async.cg.shared.global [%0], [%1], 16;" :: "r"(dst), "l"(src) : "memory")
#define CP_COMMIT()  asm volatile("cp.async.commit_group;" ::: "memory")
#define CP_WAIT0()   asm volatile("cp.async.wait_group 0;" ::: "memory")

#define LDMATRIX_X4(r0, r1, r2, r3, addr) \
    asm volatile("ldmatrix.sync.aligned.m8n8.x4.shared.b16 {%0,%1,%2,%3}, [%4];" \
                 : "=r"(r0), "=r"(r1), "=r"(r2), "=r"(r3) : "r"(addr))

#define MMA16816(c, a0, a1, a2, a3, b0, b1) \
    asm volatile("mma.sync.aligned.m16n8k16.row.col.f32.bf16.bf16.f32 " \
                 "{%0,%1,%2,%3}, {%4,%5,%6,%7}, {%8,%9}, {%0,%1,%2,%3};" \
                 : "+f"((c)[0]), "+f"((c)[1]), "+f"((c)[2]), "+f"((c)[3]) \
                 : "r"(a0), "r"(a1), "r"(a2), "r"(a3), "r"(b0), "r"(b1))

// ---- pre-pass: queue f32 -> bf16 (once per launch) ----
__global__ void queue_to_bf16_kernel(const float* __restrict__ queue)
{
    int i = (blockIdx.x * blockDim.x + threadIdx.x) * 2;
    float2 v = *(const float2*)(queue + i);
    __nv_bfloat162 b;
    b.x = __float2bfloat16(v.x);
    b.y = __float2bfloat16(v.y);
    *(__nv_bfloat162*)(g_queue_bf + i) = b;
}

__global__ __launch_bounds__(NTHREADS, 1)
void pcl_hmma_kernel(const float* __restrict__ feats,
                     const int*   __restrict__ labels,
                     float*       __restrict__ out)
{
    extern __shared__ char smem[];
    const uint32_t sb   = smem_u32(smem);
    const int tid  = threadIdx.x;
    const int warp = tid >> 5;
    const int lane = tid & 31;
    const int pix0 = blockIdx.x * TILE_P;

    // feats [b,c,h,w]; TILE_P divides HW so a CTA never crosses an image
    const float* fbase = feats + (size_t)(pix0 / HW) * C_DIM * HW + (pix0 % HW);

    // ---- B staging: whole 128KB queue via cp.async, swizzled ----
    {
        #pragma unroll
        for (int i = 0; i < 16; i++) {
            int q   = tid + NTHREADS * i;        // 0..8191 16B-chunks
            int cls = q >> 5;
            int c   = q & 31;
            uint32_t dst = sb + SM_B + cls * 512 + ((c ^ (cls & 7)) << 4);
            const void* src = (const char*)g_queue_bf + cls * 512 + c * 16;
            CP_ASYNC16(dst, src);
        }
        CP_COMMIT();
    }

    // ---- A staging roles: thread = (chg 0..3, pixA 0..127), 8 channels each ----
    const int pixA = tid & 127;
    const int chg  = tid >> 7;
    const uint32_t a_st_off = pixA * 64 + ((chg ^ ((pixA >> 1) & 3)) << 4);

    float areg[8];
    auto loadA = [&](int ks) {
        #pragma unroll
        for (int j = 0; j < 8; j++)
            areg[j] = __ldg(fbase + (size_t)(ks * KB + chg * 8 + j) * HW + pixA);
    };
    auto storeA = [&](uint32_t abase) {
        uint4 w;
        w.x = pkbf2(areg[0], areg[1]);
        w.y = pkbf2(areg[2], areg[3]);
        w.z = pkbf2(areg[4], areg[5]);
        w.w = pkbf2(areg[6], areg[7]);
        asm volatile("st.shared.v4.b32 [%0], {%1,%2,%3,%4};"
                     :: "r"(abase + a_st_off), "r"(w.x), "r"(w.y), "r"(w.z), "r"(w.w) : "memory");
    };

    loadA(0);
    storeA(sb + SM_A0);
    CP_WAIT0();
    __syncthreads();

    // ---- warp tiling: 16 warps = 4(pix) x 4(cls); warp tile 32 pix x 64 cls ----
    const int wm = warp & 3;     // pixel coord  -> rows wm*32..+31
    const int wn = warp >> 2;    // class coord  -> cols wn*64..+63

    // A ldmatrix lane addressing: row = lane&15 (pixel), ksel = lane>>4
    const int arow0 = wm * 32 + (lane & 15);          // mi=0 pixel row
    const int ksel  = lane >> 4;
    const uint32_t a_ld_base[2] = {
        (uint32_t)(arow0 * 64),            // + swizzled chunk
        (uint32_t)((arow0 + 16) * 64)
    };
    const uint32_t a_swz[2] = { (uint32_t)((arow0 >> 1) & 3),
                                (uint32_t)(((arow0 + 16) >> 1) & 3) };

    // B ldmatrix lane addressing
    const int bg   = lane & 7;
    const int bsel = lane >> 3;                        // 0..3
    const int bcls = wn * 64 + bg + ((bsel >= 2) ? 8 : 0);
    const int bkh  = bsel & 1;
    const uint32_t b_ld_row = sb + SM_B + bcls * 512;  // + ((kchunk)^bg)*16

    float acc[2][8][4];
    #pragma unroll
    for (int mi = 0; mi < 2; mi++)
        #pragma unroll
        for (int ni = 0; ni < 8; ni++)
            #pragma unroll
            for (int r = 0; r < 4; r++) acc[mi][ni][r] = 0.0f;

    // ---- mainloop: 8 chunks of 32 channels, double-buffered A ----
    #pragma unroll 1
    for (int ks = 0; ks < NKS; ks++) {
        if (ks < NKS - 1) loadA(ks + 1);

        const uint32_t acur = sb + ((ks & 1) ? SM_A1 : SM_A0);
        #pragma unroll
        for (int kf = 0; kf < 2; kf++) {
            uint32_t afr[2][4];
            #pragma unroll
            for (int mi = 0; mi < 2; mi++) {
                uint32_t addr = acur + a_ld_base[mi] +
                                (((uint32_t)(kf * 2 + ksel) ^ a_swz[mi]) << 4);
                LDMATRIX_X4(afr[mi][0], afr[mi][1], afr[mi][2], afr[mi][3], addr);
            }
            const uint32_t kchunk = ks * 4 + kf * 2 + bkh;
            #pragma unroll
            for (int nt = 0; nt < 4; nt++) {
                uint32_t b0, b1, b2, b3;
                uint32_t addr = b_ld_row + nt * 8192 + (((kchunk) ^ (uint32_t)bg) << 4);
                LDMATRIX_X4(b0, b1, b2, b3, addr);
                #pragma unroll
                for (int mi = 0; mi < 2; mi++) {
                    MMA16816(acc[mi][nt * 2 + 0], afr[mi][0], afr[mi][1], afr[mi][2], afr[mi][3], b0, b1);
                    MMA16816(acc[mi][nt * 2 + 1], afr[mi][0], afr[mi][1], afr[mi][2], afr[mi][3], b2, b3);
                }
            }
        }

        if (ks < NKS - 1) {
            storeA(sb + (((ks + 1) & 1) ? SM_A1 : SM_A0));
            __syncthreads();
        }
    }

    // ---- register epilogue: exp + mask + per-pixel partial sums ----
    // acc mapping: c0=D[g][2t], c1=D[g][2t+1], c2=D[g+8][2t], c3=D[g+8][2t+1]
    const int g = lane >> 2;
    const int t = lane & 3;
    float* red_sn = (float*)(smem + SM_RED);            // [4][128]
    float* red_sp = (float*)(smem + SM_RED + 2048);     // [4][128]
    float* wpart  = (float*)(smem + SM_RED + 4096);     // [8]

    #pragma unroll
    for (int mi = 0; mi < 2; mi++) {
        #pragma unroll
        for (int h = 0; h < 2; h++) {
            const int pixel = wm * 32 + mi * 16 + h * 8 + g;
            const int* lrow = labels + (size_t)(pix0 + pixel) * M_CLS + wn * 64 + t * 2;
            int2 lab[8];
            #pragma unroll
            for (int ni = 0; ni < 8; ni++)
                lab[ni] = __ldg((const int2*)(lrow + ni * 8));
            float sn = 0.0f, sp = 0.0f;
            #pragma unroll
            for (int ni = 0; ni < 8; ni++) {
                float v0 = acc[mi][ni][h * 2 + 0] * INV_T;
                float v1 = acc[mi][ni][h * 2 + 1] * INV_T;
                float e0 = __expf(lab[ni].x ? -v0 : v0);
                float e1 = __expf(lab[ni].y ? -v1 : v1);
                if (lab[ni].x) sp += e0; else sn += e0;
                if (lab[ni].y) sp += e1; else sn += e1;
            }
            sn += __shfl_xor_sync(0xFFFFFFFFu, sn, 1);
            sn += __shfl_xor_sync(0xFFFFFFFFu, sn, 2);
            sp += __shfl_xor_sync(0xFFFFFFFFu, sp, 1);
            sp += __shfl_xor_sync(0xFFFFFFFFu, sp, 2);
            if (t == 0) {
                red_sn[wn * 128 + pixel] = sn;
                red_sp[wn * 128 + pixel] = sp;
            }
        }
    }
    __syncthreads();

    // ---- combine 4 class-slices per pixel, loss, block reduction ----
    float th_loss = 0.0f, th_cnt = 0.0f;
    if (tid < 128) {
        float tsn = red_sn[tid] + red_sn[128 + tid] + red_sn[256 + tid] + red_sn[384 + tid];
        float tsp = red_sp[tid] + red_sp[128 + tid] + red_sp[256 + tid] + red_sp[384 + tid];
        float loss = logf(tsn * tsp + 1.0f);
        th_loss = loss;
        th_cnt  = (loss != 0.0f) ? 1.0f : 0.0f;
        #pragma unroll
        for (int o = 16; o > 0; o >>= 1) {
            th_loss += __shfl_xor_sync(0xFFFFFFFFu, th_loss, o);
            th_cnt  += __shfl_xor_sync(0xFFFFFFFFu, th_cnt,  o);
        }
        if (lane == 0) { wpart[warp] = th_loss; wpart[warp + 4] = th_cnt; }
    }
    __syncthreads();

    __shared__ bool is_last;
    if (tid == 0) {
        float s = wpart[0] + wpart[1] + wpart[2] + wpart[3];
        float c = wpart[4] + wpart[5] + wpart[6] + wpart[7];
        g_partials[blockIdx.x] = make_float2(s, c);
        __threadfence();
        unsigned old = atomicAdd(&g_done, 1u);
        is_last = (old == NBLOCKS - 1);
    }
    __syncthreads();

    // ---- last arriving block: deterministic final reduction ----
    if (is_last) {
        double s = 0.0;
        float  c = 0.0f;
        #pragma unroll
        for (int it = 0; it < NBLOCKS / NTHREADS; it++) {
            float2 p = g_partials[tid + it * NTHREADS];
            s += (double)p.x;
            c += p.y;
        }
        __shared__ double ssum[NTHREADS];
        __shared__ float  scnt[NTHREADS];
        ssum[tid] = s;
        scnt[tid] = c;
        __syncthreads();
        for (int o = NTHREADS / 2; o > 0; o >>= 1) {
            if (tid < o) { ssum[tid] += ssum[tid + o]; scnt[tid] += scnt[tid + o]; }
            __syncthreads();
        }
        if (tid == 0) {
            float cnt = scnt[0];
            out[0] = (cnt == 0.0f) ? 0.0f : (float)(ssum[0] / (double)fmaxf(cnt, 1.0f));
            __threadfence();
            g_done = 0;
        }
    }
}

extern "C" void kernel_launch(void* const* d_in, const int* in_sizes, int n_in,
                              void* d_out, int out_size)
{
    // metadata.txt order: feats (f32), queue (f32), labels (i32).
    // feats and labels have identical element counts — positional ID only.
    const float* feats  = (const float*)d_in[0];
    const float* queue  = (const float*)d_in[1];
    const int*   labels = (const int*)d_in[2];

    cudaFuncSetAttribute(pcl_hmma_kernel,
                         cudaFuncAttributeMaxDynamicSharedMemorySize, SMEM_BYTES);

    queue_to_bf16_kernel<<<M_CLS * C_DIM / (2 * 256), 256>>>(queue);
    pcl_hmma_kernel<<<NBLOCKS, NTHREADS, SMEM_BYTES>>>(feats, labels, (float*)d_out);
}